// round 13
// baseline (speedup 1.0000x reference)
#include <cuda_runtime.h>
#include <cstdint>

#define NS 512
#define NV 32000
#define NB 16
#define NT 128

// ---- scratch (no cudaMalloc allowed) ----
__device__ float g_lse_em[NS];
__device__ float g_pi[NS];
__device__ float g_PT[NS * NS];          // PT[c][s] = softmax(tm)[s][c]
__device__ float g_E[NB * NT * NS];      // E[b][t][s] = exp(log_em[s, x_bt])
__device__ float g_L[NB];                // per-batch log-likelihood

// ---- helpers ----
__device__ __forceinline__ unsigned smem_u32(const void* p) {
    return (unsigned)__cvta_generic_to_shared(p);
}
__device__ __forceinline__ unsigned mapa_u32(unsigned local, unsigned rank) {
    unsigned r;
    asm("mapa.shared::cluster.u32 %0, %1, %2;" : "=r"(r) : "r"(local), "r"(rank));
    return r;
}
#define MBAR_INIT(mb, cnt) \
    asm volatile("mbarrier.init.shared.b64 [%0], %1;" :: "r"(mb), "r"(cnt) : "memory")
#define MBAR_INVAL(mb) \
    asm volatile("mbarrier.inval.shared.b64 [%0];" :: "r"(mb) : "memory")
#define MBAR_EXPECT_TX(mb, bytes) \
    asm volatile("mbarrier.arrive.expect_tx.shared.b64 _, [%0], %1;" :: "r"(mb), "r"(bytes) : "memory")
// HW-sleep wait (suspend hint keeps spinners off the SMEM port)
#define MBAR_WAIT_CLUSTER(mb, parity) do {                                                       \
    asm volatile("{\n\t.reg .pred P;\n\tW%=:\n\t"                                                \
        "mbarrier.try_wait.parity.acquire.cluster.shared::cta.b64 P, [%0], %1, 0x989680;\n\t"    \
        "@!P bra W%=;\n\t}" :: "r"(mb), "r"(parity) : "memory");                                 \
} while (0)
__device__ __forceinline__ void st_async_v4(unsigned raddr, float4 v, unsigned rmbar) {
    asm volatile(
        "st.async.shared::cluster.mbarrier::complete_tx::bytes.v4.f32 "
        "[%0], {%1, %2, %3, %4}, [%5];"
        :: "r"(raddr), "f"(v.x), "f"(v.y), "f"(v.z), "f"(v.w), "r"(rmbar) : "memory");
}
// packed f32x2 math
#define FMA2(d, a, b, c) \
    asm("fma.rn.f32x2 %0, %1, %2, %3;" : "=l"(d) : "l"(a), "l"(b), "l"(c))
#define ADD2(d, a, b) \
    asm("add.rn.f32x2 %0, %1, %2;" : "=l"(d) : "l"(a), "l"(b))
__device__ __forceinline__ float hadd2(unsigned long long v) {
    float lo, hi;
    asm("mov.b64 {%0, %1}, %2;" : "=f"(lo), "=f"(hi) : "l"(v));
    return lo + hi;
}

// ===================== K_pre: fused em-LSE + softmax(tm), softmax(p) ============
// blocks [0, NS): row-logsumexp of em[row, 0:32000] -> g_lse_em
// blocks [NS, 2*NS]: softmax row of tm (or p for the last block), 256 threads.
__global__ void k_pre(const float* __restrict__ em, const float* __restrict__ tm,
                      const float* __restrict__ p) {
    __shared__ float sm[8];
    __shared__ float red;
    const int tid = threadIdx.x;   // 256

    if (blockIdx.x < NS) {
        const int row = blockIdx.x;
        const float4* r = (const float4*)(em + (size_t)row * NV);
        const int n4 = NV / 4;  // 8000

        float m = -1e30f;
        for (int i = tid; i < n4; i += blockDim.x) {
            float4 x = r[i];
            m = fmaxf(m, fmaxf(fmaxf(x.x, x.y), fmaxf(x.z, x.w)));
        }
        #pragma unroll
        for (int o = 16; o; o >>= 1) m = fmaxf(m, __shfl_xor_sync(~0u, m, o));
        if ((tid & 31) == 0) sm[tid >> 5] = m;
        __syncthreads();
        if (tid < 32) {
            float mm = (tid < 8) ? sm[tid] : -1e30f;
            #pragma unroll
            for (int o = 4; o; o >>= 1) mm = fmaxf(mm, __shfl_xor_sync(~0u, mm, o));
            if (tid == 0) red = mm;
        }
        __syncthreads();
        m = red;
        __syncthreads();

        float s = 0.f;
        for (int i = tid; i < n4; i += blockDim.x) {
            float4 x = r[i];
            s += __expf(x.x - m) + __expf(x.y - m) + __expf(x.z - m) + __expf(x.w - m);
        }
        #pragma unroll
        for (int o = 16; o; o >>= 1) s += __shfl_xor_sync(~0u, s, o);
        if ((tid & 31) == 0) sm[tid >> 5] = s;
        __syncthreads();
        if (tid == 0) {
            float tot = 0.f;
            #pragma unroll
            for (int wi = 0; wi < 8; wi++) tot += sm[wi];
            g_lse_em[row] = m + __logf(tot);
        }
    } else {
        const int row = blockIdx.x - NS;           // 0..NS (NS == p row)
        const float* src = (row < NS) ? (tm + (size_t)row * NS) : p;

        float x0 = src[tid], x1 = src[tid + 256];
        float m = fmaxf(x0, x1);
        #pragma unroll
        for (int o = 16; o; o >>= 1) m = fmaxf(m, __shfl_xor_sync(~0u, m, o));
        if ((tid & 31) == 0) sm[tid >> 5] = m;
        __syncthreads();
        if (tid == 0) {
            float mm = sm[0];
            #pragma unroll
            for (int wi = 1; wi < 8; wi++) mm = fmaxf(mm, sm[wi]);
            red = mm;
        }
        __syncthreads();
        m = red;
        __syncthreads();

        float s = __expf(x0 - m) + __expf(x1 - m);
        #pragma unroll
        for (int o = 16; o; o >>= 1) s += __shfl_xor_sync(~0u, s, o);
        if ((tid & 31) == 0) sm[tid >> 5] = s;
        __syncthreads();
        if (tid == 0) {
            float tot = 0.f;
            #pragma unroll
            for (int wi = 0; wi < 8; wi++) tot += sm[wi];
            red = m + __logf(tot);
        }
        __syncthreads();
        const float lse = red;

        if (row < NS) {
            g_PT[(size_t)(tid)       * NS + row] = __expf(x0 - lse);
            g_PT[(size_t)(tid + 256) * NS + row] = __expf(x1 - lse);
        } else {
            g_pi[tid]       = __expf(x0 - lse);
            g_pi[tid + 256] = __expf(x1 - lse);
        }
    }
}

// ===================== K_gather: E[b][t][s] = exp(em[s, id] - lse_em[s]) ========
__global__ void k_gather(const float* __restrict__ em, const int* __restrict__ ids) {
    const int bt = blockIdx.x;           // 0..2047
    int id = ids[bt];
    id = (id < 0) ? 0 : ((id >= NV) ? NV - 1 : id);
    const float* col = em + id;
    #pragma unroll
    for (int k = 0; k < 4; k++) {
        int s = threadIdx.x + 128 * k;   // blockDim = 128
        g_E[(size_t)bt * NS + s] = __expf(col[(size_t)s * NV] - g_lse_em[s]);
    }
}

// ===================== K4: clustered scaled-forward recurrence ==================
// 16 clusters x 8 CTAs x 512 threads; P^T chunk in packed f32x2 registers.
// Step body compile-time specialized on the slot (macro, 2x-unrolled steady
// state): no per-iter slot SELs. Warp 15 (highest arbiter priority) is the
// elected mbar waiter; bar.sync broadcasts. Arm-after-wait on the same mbar
// (race-free: producers of v_{t+1} must first consume our v_t push, which
// follows the arm). rcp.approx for the scale; e4 loaded inline (L2-covered).
//
// HMM_STEP(T_, SP_, DOWAIT_, DOARM_): reads buf[SP_], pushes slot 1-SP_.
#define HMM_STEP(T_, SP_, DOWAIT_, DOARM_) do {                                   \
    if (DOWAIT_) {                                                                \
        if (w == 15) MBAR_WAIT_CLUSTER((SP_) ? mb1 : mb0, ph[SP_]);               \
        __syncthreads();                                                          \
        ph[SP_] ^= 1;                                                             \
    }                                                                             \
    if ((DOARM_) && tid == 0) MBAR_EXPECT_TX((SP_) ? mb1 : mb0, 2048u);           \
    const float4 e4 = *(const float4*)&Eb[(T_) * NS + colbase];                   \
    const float* cur = buf[SP_];                                                  \
    unsigned long long acc0 = 0, acc1 = 0, acc2 = 0, acc3 = 0, ssA = 0, ssB = 0;  \
    _Pragma("unroll")                                                             \
    for (int k = 0; k < 4; k++) {                                                 \
        ulonglong2 aa = *(const ulonglong2*)&cur[4 * l + 128 * k];                \
        FMA2(acc0, aa.x, Pa[0][k], acc0); FMA2(acc0, aa.y, Pb[0][k], acc0);       \
        FMA2(acc1, aa.x, Pa[1][k], acc1); FMA2(acc1, aa.y, Pb[1][k], acc1);       \
        FMA2(acc2, aa.x, Pa[2][k], acc2); FMA2(acc2, aa.y, Pb[2][k], acc2);       \
        FMA2(acc3, aa.x, Pa[3][k], acc3); FMA2(acc3, aa.y, Pb[3][k], acc3);       \
        ADD2(ssA, ssA, aa.x); ADD2(ssB, ssB, aa.y);                               \
    }                                                                             \
    ADD2(ssA, ssA, ssB);                                                          \
    float a0 = hadd2(acc0), a1 = hadd2(acc1), a2 = hadd2(acc2), a3 = hadd2(acc3); \
    float ss = hadd2(ssA);                                                        \
    float p0 = (l & 16) ? a2 : a0, q0 = (l & 16) ? a0 : a2;                       \
    float p1 = (l & 16) ? a3 : a1, q1 = (l & 16) ? a1 : a3;                       \
    p0 += __shfl_xor_sync(~0u, q0, 16);                                           \
    p1 += __shfl_xor_sync(~0u, q1, 16);                                           \
    float pp = (l & 8) ? p1 : p0, qq = (l & 8) ? p0 : p1;                         \
    pp += __shfl_xor_sync(~0u, qq, 8);                                            \
    pp += __shfl_xor_sync(~0u, pp, 4);                                            \
    pp += __shfl_xor_sync(~0u, pp, 2);                                            \
    pp += __shfl_xor_sync(~0u, pp, 1);                                            \
    _Pragma("unroll")                                                             \
    for (int o = 16; o; o >>= 1) ss += __shfl_xor_sync(~0u, ss, o);               \
    float invS; asm("rcp.approx.f32 %0, %1;" : "=f"(invS) : "f"(ss));             \
    const int lb = l & 7;                                                         \
    const float v0 = __shfl_sync(~0u, pp, lb);                                    \
    const float v1 = __shfl_sync(~0u, pp, 8 + lb);                                \
    const float v2 = __shfl_sync(~0u, pp, 16 + lb);                               \
    const float v3 = __shfl_sync(~0u, pp, 24 + lb);                               \
    if (l < 8) {                                                                  \
        float4 v;                                                                 \
        v.x = v0 * invS * e4.x;                                                   \
        v.y = v1 * invS * e4.y;                                                   \
        v.z = v2 * invS * e4.z;                                                   \
        v.w = v3 * invS * e4.w;                                                   \
        st_async_v4(rbuf + (unsigned)((((1 - (SP_)) * NS) + colbase) * 4), v,     \
                    (SP_) ? rmb0 : rmb1);                                         \
    }                                                                             \
    if (rank == 0 && tid == 0) L += __logf(ss);                                   \
} while (0)

__global__ void __cluster_dims__(8, 1, 1) __launch_bounds__(512, 1) k_forward() {
    __shared__ __align__(16) float buf[2][NS];
    __shared__ __align__(8) unsigned long long mbars[2];

    const int tid = threadIdx.x;
    const int w = tid >> 5;
    const int l = tid & 31;
    unsigned rank;
    asm("mov.u32 %0, %%cluster_ctarank;" : "=r"(rank));
    const int g = blockIdx.x >> 3;                 // batch / cluster id
    const int colbase = (int)rank * 64 + w * 4;    // this warp's 4 columns

    // --- P^T chunk into packed registers ---
    unsigned long long Pa[4][4], Pb[4][4];
    #pragma unroll
    for (int j = 0; j < 4; j++)
        #pragma unroll
        for (int k = 0; k < 4; k++) {
            ulonglong2 pp = *(const ulonglong2*)&g_PT[(size_t)(colbase + j) * NS + 4 * l + 128 * k];
            Pa[j][k] = pp.x;
            Pb[j][k] = pp.y;
        }

    const unsigned mb0 = smem_u32(&mbars[0]);
    const unsigned mb1 = smem_u32(&mbars[1]);
    if (tid == 0) {
        MBAR_INIT(mb0, 1); MBAR_INIT(mb1, 1);
        MBAR_EXPECT_TX(mb1, 2048u);   // arm for v1 receptions (slot 1)
    }

    const float* Eb = g_E + (size_t)g * NT * NS;

    // --- t = 0: every CTA computes the full v0 = pi * E0 locally ---
    buf[0][tid] = g_pi[tid] * Eb[tid];
    __syncthreads();
    // peers' mbarriers must be initialized+armed before any st.async targets them
    asm volatile("barrier.cluster.arrive.aligned;" ::: "memory");
    asm volatile("barrier.cluster.wait.aligned;"   ::: "memory");

    // --- per-lane remote addresses (lanes 0..7 push to peer = lane index) ---
    unsigned rbuf = 0, rmb0 = 0, rmb1 = 0;
    if (l < 8) {
        rbuf = mapa_u32(smem_u32(&buf[0][0]), (unsigned)l);
        rmb0 = mapa_u32(mb0, (unsigned)l);
        rmb1 = mapa_u32(mb1, (unsigned)l);
    }

    int ph[2] = {0, 0};
    float L = 0.f;

    // t=1: prev local in slot 0, no wait; arm mb0 (for v2 into slot 0)
    HMM_STEP(1, 0, false, true);
    // steady state, 2x unrolled: (t even: SP=1) then (t odd: SP=0)
    for (int t = 2; t < 126; t += 2) {
        HMM_STEP(t,     1, true, true);
        HMM_STEP(t + 1, 0, true, true);
    }
    HMM_STEP(126, 1, true, true);
    HMM_STEP(127, 0, true, false);   // last arm skipped (balanced phases)

    // --- final S_{T-1} term: v_127 in slot 1 / mb1 ---
    if (w == 15) MBAR_WAIT_CLUSTER(mb1, ph[1]);
    __syncthreads();
    {
        const float* cur = buf[1];
        unsigned long long ssp = 0;
        #pragma unroll
        for (int k = 0; k < 4; k++) {
            ulonglong2 aa = *(const ulonglong2*)&cur[4 * l + 128 * k];
            ADD2(ssp, ssp, aa.x); ADD2(ssp, ssp, aa.y);
        }
        float ss = hadd2(ssp);
        #pragma unroll
        for (int o = 16; o; o >>= 1) ss += __shfl_xor_sync(~0u, ss, o);
        if (rank == 0 && tid == 0) {
            L += __logf(ss);
            g_L[g] = L;
        }
    }
    __syncthreads();
    if (tid == 0) { MBAR_INVAL(mb0); MBAR_INVAL(mb1); }  // clean for next replay
    // align exits: no CTA leaves while a peer could still target its smem
    asm volatile("barrier.cluster.arrive.aligned;" ::: "memory");
    asm volatile("barrier.cluster.wait.aligned;"   ::: "memory");
}

// ===================== K5: loss = -mean_b L[b] ===================================
__global__ void k_final(float* __restrict__ out) {
    if (threadIdx.x == 0) {
        float s = 0.f;
        #pragma unroll
        for (int i = 0; i < NB; i++) s += g_L[i];
        out[0] = -s / (float)NB;
    }
}

// ===================== launch ====================================================
extern "C" void kernel_launch(void* const* d_in, const int* in_sizes, int n_in,
                              void* d_out, int out_size) {
    const float* em = nullptr;
    const float* tm = nullptr;
    const float* p  = nullptr;
    const int* ids  = nullptr;
    for (int i = 0; i < n_in; i++) {
        if (in_sizes[i] == NB * NT)      ids = (const int*)d_in[i];
        else if (in_sizes[i] == NS * NV) em  = (const float*)d_in[i];
        else if (in_sizes[i] == NS * NS) tm  = (const float*)d_in[i];
        else if (in_sizes[i] == NS)      p   = (const float*)d_in[i];
    }

    k_pre<<<2 * NS + 1, 256>>>(em, tm, p);
    k_gather<<<NB * NT, 128>>>(em, ids);

    {
        cudaLaunchConfig_t cfg = {};
        cfg.gridDim  = dim3(NB * 8, 1, 1);
        cfg.blockDim = dim3(512, 1, 1);
        cfg.dynamicSmemBytes = 0;
        cfg.stream = 0;
        cudaLaunchAttribute attrs[1];
        attrs[0].id = cudaLaunchAttributeClusterDimension;
        attrs[0].val.clusterDim.x = 8;
        attrs[0].val.clusterDim.y = 1;
        attrs[0].val.clusterDim.z = 1;
        cfg.attrs = attrs;
        cfg.numAttrs = 1;
        cudaLaunchKernelEx(&cfg, k_forward);
    }

    k_final<<<1, 32>>>((float*)d_out);
}